// round 13
// baseline (speedup 1.0000x reference)
#include <cuda_runtime.h>
#include <cuda_fp16.h>
#include <cstdint>
#include <math.h>

#define E_BONDS   131072
#define N_ATOMS_  65536
#define HID       256
#define AFD       143
#define KIN       157
#define KIN_P     160
#define KCAT_P    416
#define BMOL      2048

#define EH  ((size_t)E_BONDS * HID)
#define NH  ((size_t)N_ATOMS_ * HID)
__device__ float g_scratch[127 * 1024 * 1024];

__device__ __forceinline__ uint32_t smem_u32(const void* p) {
    uint32_t a;
    asm("{ .reg .u64 t; cvta.to.shared.u64 t, %1; cvt.u32.u64 %0, t; }"
        : "=r"(a) : "l"(p));
    return a;
}
__device__ __forceinline__ void cp_async16(uint32_t dst, const void* src) {
    asm volatile("cp.async.cg.shared.global [%0], [%1], 16;"
                 :: "r"(dst), "l"(src));
}
#define CP_COMMIT() asm volatile("cp.async.commit_group;" ::: "memory")
#define CP_WAIT0()  asm volatile("cp.async.wait_group 0;" ::: "memory")
#define CP_WAIT2()  asm volatile("cp.async.wait_group 2;" ::: "memory")

// ---------------------------------------------------------------------------
// conversions / padding
// ---------------------------------------------------------------------------
__global__ void w2h_all(const float* __restrict__ s1, const float* __restrict__ s3,
                        const float* __restrict__ s4, __half* __restrict__ dst,
                        float* __restrict__ zbuf, int zn)
{
    int i = blockIdx.x * 256 + threadIdx.x;
    if (i < zn) zbuf[i] = 0.f;
    const int n1 = HID * 256, n3 = 2 * HID * 256, n4 = 3 * HID * 256;
    if (i >= n4) return;
    float v;
    if      (i < n1) v = s1[i];
    else if (i < n3) v = s3[i - n1];
    else             v = s4[i - n3];
    dst[i] = __float2half(v);
}

__global__ void build_wi(const float* __restrict__ W, __half* __restrict__ dst)
{
    int i = blockIdx.x * 256 + threadIdx.x;
    if (i >= KIN_P * 256) return;
    const int r = i >> 8;
    dst[i] = __float2half(r < KIN ? W[i] : 0.f);
}

__global__ void build_wo(const float* __restrict__ W, __half* __restrict__ dst)
{
    int i = blockIdx.x * 256 + threadIdx.x;
    if (i >= KCAT_P * 256) return;
    const int r = i >> 8, c = i & 255;
    float v = 0.f;
    if (r < 143)                  v = W[r * 256 + c];
    else if (r >= 144 && r < 400) v = W[(r - 1) * 256 + c];
    dst[i] = __float2half(v);
}

__global__ void fb_conv(const float* __restrict__ fb, __half* __restrict__ dst)
{
    int i = blockIdx.x * 256 + threadIdx.x;
    if (i >= E_BONDS * 20) return;
    const int e = i / 20, g = i - e * 20;
    const float* src = fb + (size_t)e * KIN + g * 8;
    __align__(16) __half hb[8];
#pragma unroll
    for (int k = 0; k < 8; k++) {
        const int c = g * 8 + k;
        hb[k] = __float2half(c < KIN ? src[k] : 0.f);
    }
    *(uint4*)&dst[(size_t)e * KIN_P + g * 8] = *(uint4*)hb;
}

__global__ void fa_conv(const float* __restrict__ fa, __half* __restrict__ cat)
{
    int i = blockIdx.x * 256 + threadIdx.x;
    if (i >= N_ATOMS_ * 22) return;
    const int n = i / 22, g = i - n * 22;
    __align__(16) __half hb[8];
    if (g < 20) {
        const float* src = fa + (size_t)n * AFD + g * 8;
#pragma unroll
        for (int k = 0; k < 8; k++) {
            const int c = g * 8 + k;
            hb[k] = __float2half(c < AFD ? src[k] : 0.f);
        }
        *(uint4*)&cat[(size_t)n * KCAT_P + g * 8] = *(uint4*)hb;
    } else {
        uint4 z = make_uint4(0, 0, 0, 0);
        *(uint4*)&cat[(size_t)n * KCAT_P + 400 + (g - 20) * 8] = z;
    }
}

// ---------------------------------------------------------------------------
// hgemm: 4-stage cp.async ring, K-chunk 32, block 128x128 (grid.y=2), fp16 A
// ---------------------------------------------------------------------------
#define LDA_H 40
#define LDB_H 136
#define SA_EL (128 * LDA_H)
#define SB_EL (32 * LDB_H)
#define ST_EL (SA_EL + SB_EL)
#define HG_SMEM (4 * ST_EL * 2)

template<bool HAS_BIAS, bool RELU, bool OUTH, bool RAWH, bool SCOREF>
__global__ void __launch_bounds__(256, 2) hgemm(
    int M, int K,
    const __half* __restrict__ Ah, int ldah,
    const __half* __restrict__ B,
    const float* __restrict__ bias,
    __half* __restrict__ outh,
    __half* __restrict__ rawh,
    const float* __restrict__ wma,
    float* __restrict__ scores_out)
{
    extern __shared__ __align__(16) __half smh[];

    const int tid  = threadIdx.x;
    const int wid  = tid >> 5;
    const int lane = tid & 31;
    const int m0   = blockIdx.x * 128;
    const int n0   = blockIdx.y * 128;
    const int wm   = (wid & 3) * 32;
    const int wn   = (wid >> 2) * 64;
    const int S    = K >> 5;

    float acc[2][8][4];
#pragma unroll
    for (int t = 0; t < 2; t++)
#pragma unroll
        for (int j = 0; j < 8; j++)
#pragma unroll
            for (int q = 0; q < 4; q++) acc[t][j][q] = 0.f;

    const int lrow = lane & 15;
    const int lcof = (lane >> 4) * 8;

    auto stage = [&](int s) {
        const int k0 = s * 32;
        __half* bA = smh + (s & 3) * ST_EL;
        __half* bB = bA + SA_EL;
#pragma unroll
        for (int it = 0; it < 2; it++) {
            const int id = tid + it * 256;
            const int r  = id >> 4;
            const int c8 = (id & 15) * 8;
            cp_async16(smem_u32(&bB[r * LDB_H + c8]),
                       &B[(size_t)(k0 + r) * 256 + n0 + c8]);
        }
#pragma unroll
        for (int it = 0; it < 2; it++) {
            const int id  = tid + it * 256;
            const int r   = id >> 2;
            const int c16 = (id & 3) * 8;
            cp_async16(smem_u32(&bA[r * LDA_H + c16]),
                       &Ah[(size_t)(m0 + r) * ldah + k0 + c16]);
        }
        CP_COMMIT();
    };

#pragma unroll
    for (int p = 0; p < 3; p++) {
        if (p < S) stage(p); else CP_COMMIT();
    }

    for (int s = 0; s < S; s++) {
        CP_WAIT2();
        __syncthreads();
        if (s + 3 < S) stage(s + 3); else CP_COMMIT();

        __half* bA = smh + (s & 3) * ST_EL;
        __half* bB = bA + SA_EL;
#pragma unroll
        for (int ks = 0; ks < 2; ks++) {
            uint32_t fa[2][4];
#pragma unroll
            for (int t = 0; t < 2; t++) {
                const uint32_t ad = smem_u32(&bA[(wm + t * 16 + lrow) * LDA_H + ks * 16 + lcof]);
                asm volatile("ldmatrix.sync.aligned.m8n8.x4.shared.b16 {%0,%1,%2,%3}, [%4];"
                             : "=r"(fa[t][0]), "=r"(fa[t][1]), "=r"(fa[t][2]), "=r"(fa[t][3])
                             : "r"(ad));
            }
            uint32_t fb[8][2];
#pragma unroll
            for (int nt = 0; nt < 4; nt++) {
                const uint32_t ad = smem_u32(&bB[(ks * 16 + lrow) * LDB_H + wn + nt * 16 + lcof]);
                uint32_t r0, r1, r2, r3;
                asm volatile("ldmatrix.sync.aligned.m8n8.x4.trans.shared.b16 {%0,%1,%2,%3}, [%4];"
                             : "=r"(r0), "=r"(r1), "=r"(r2), "=r"(r3) : "r"(ad));
                fb[nt * 2][0] = r0; fb[nt * 2][1] = r1;
                fb[nt * 2 + 1][0] = r2; fb[nt * 2 + 1][1] = r3;
            }
#pragma unroll
            for (int t = 0; t < 2; t++)
#pragma unroll
                for (int j = 0; j < 8; j++)
                    asm volatile(
                        "mma.sync.aligned.m16n8k16.row.col.f32.f16.f16.f32 "
                        "{%0,%1,%2,%3}, {%4,%5,%6,%7}, {%8,%9}, {%0,%1,%2,%3};"
                        : "+f"(acc[t][j][0]), "+f"(acc[t][j][1]),
                          "+f"(acc[t][j][2]), "+f"(acc[t][j][3])
                        : "r"(fa[t][0]), "r"(fa[t][1]), "r"(fa[t][2]), "r"(fa[t][3]),
                          "r"(fb[j][0]), "r"(fb[j][1]));
        }
    }

    float rowdot[2][2] = {{0.f, 0.f}, {0.f, 0.f}};
#pragma unroll
    for (int t = 0; t < 2; t++) {
        const int mrow = m0 + wm + t * 16 + (lane >> 2);
#pragma unroll
        for (int j = 0; j < 8; j++) {
            const int nc = n0 + wn + j * 8 + (lane & 3) * 2;
            float wx = 0.f, wy = 0.f;
            if (SCOREF) { wx = __ldg(&wma[nc]); wy = __ldg(&wma[nc + 1]); }
#pragma unroll
            for (int hf = 0; hf < 2; hf++) {
                const size_t m = (size_t)(mrow + hf * 8);
                float vx = acc[t][j][hf * 2 + 0];
                float vy = acc[t][j][hf * 2 + 1];
                if (HAS_BIAS) { vx += bias[nc]; vy += bias[nc + 1]; }
                if (RAWH) *(__half2*)&rawh[m * 256 + nc] = __floats2half2_rn(vx, vy);
                if (RELU) { vx = fmaxf(vx, 0.f); vy = fmaxf(vy, 0.f); }
                if (OUTH) *(__half2*)&outh[m * 256 + nc] = __floats2half2_rn(vx, vy);
                if (SCOREF) rowdot[t][hf] += vx * wx + vy * wy;
            }
        }
    }
    if (SCOREF) {
#pragma unroll
        for (int t = 0; t < 2; t++)
#pragma unroll
            for (int hf = 0; hf < 2; hf++) {
                float v = rowdot[t][hf];
                v += __shfl_xor_sync(0xffffffffu, v, 1);
                v += __shfl_xor_sync(0xffffffffu, v, 2);
                if ((lane & 3) == 0)
                    atomicAdd(&scores_out[m0 + wm + t * 16 + hf * 8 + (lane >> 2)], v);
            }
    }
}

// ---------------------------------------------------------------------------
// mp_step v2: warp-autonomous. Full Wh resident in smem (one cp.async group),
// ONE __syncthreads; each warp then owns a 16-row x 128-col output slab.
// Pair p (warps 2p,2p+1) shares rows p*16..p*16+15; warp parity splits N.
// ---------------------------------------------------------------------------
#define MP_LDB 264
#define MP_LDA 264
#define MP_SWH (256 * MP_LDB)          // halves
#define MP_SA  (64 * MP_LDA)           // halves
#define MP_SMEM ((MP_SWH + MP_SA) * 2) // 168960 bytes

__global__ void __launch_bounds__(256, 1) mp_step(
    const __half* __restrict__ msg, const int* __restrict__ bgraph,
    const float* __restrict__ scores, const __half* __restrict__ Wh,
    const __half* __restrict__ binput, __half* __restrict__ msg_out,
    const float* __restrict__ wma, float* __restrict__ scores_out)
{
    extern __shared__ __align__(16) __half smh[];
    __shared__ float sred[64];
    __half* sWh = smh;
    __half* sA  = smh + MP_SWH;

    const int tid  = threadIdx.x;
    const int wid  = tid >> 5;
    const int lane = tid & 31;
    const int e0   = blockIdx.x * 64;
    const int m0r  = (wid >> 1) * 16;   // pair row base
    const int nh   = (wid & 1) * 128;   // N half

    if (tid < 64) sred[tid] = 0.f;

    // launch full-Wh load (one group)
    for (int i = tid; i < 256 * 32; i += 256) {
        const int r = i >> 5, c8 = (i & 31) * 8;
        cp_async16(smem_u32(&sWh[r * MP_LDB + c8]), &Wh[(size_t)r * 256 + c8]);
    }
    CP_COMMIT();

    // ---- gather (2-row pipeline), rows wid*8..wid*8+7 ----
    {
        int   idxr[8];
        float scr[8];
#pragma unroll
        for (int rr = 0; rr < 8; rr++) {
            const int e = e0 + wid * 8 + rr;
            int id = 0; float sc = 0.f;
            if (lane < 6) {
                id = bgraph[e * 6 + lane];
                sc = __ldg(&scores[id]);
            }
            idxr[rr] = id; scr[rr] = sc;
        }
#pragma unroll
        for (int pr = 0; pr < 4; pr++) {
            const int r0 = pr * 2, r1 = pr * 2 + 1;
            int   nb0[6], nb1[6];
            float s0[6], s1[6];
#pragma unroll
            for (int j = 0; j < 6; j++) {
                nb0[j] = __shfl_sync(0xffffffffu, idxr[r0], j);
                s0[j]  = __shfl_sync(0xffffffffu, scr[r0], j);
                nb1[j] = __shfl_sync(0xffffffffu, idxr[r1], j);
                s1[j]  = __shfl_sync(0xffffffffu, scr[r1], j);
            }
            uint4 rv0[6], rv1[6];
#pragma unroll
            for (int j = 0; j < 6; j++)
                rv0[j] = *(const uint4*)(msg + (size_t)nb0[j] * 256 + lane * 8);
#pragma unroll
            for (int j = 0; j < 6; j++)
                rv1[j] = *(const uint4*)(msg + (size_t)nb1[j] * 256 + lane * 8);

            float w0[6], w1[6];
            {
                float mx0 = s0[0], mx1 = s1[0];
#pragma unroll
                for (int j = 1; j < 6; j++) { mx0 = fmaxf(mx0, s0[j]); mx1 = fmaxf(mx1, s1[j]); }
                float sum0 = 0.f, sum1 = 0.f;
#pragma unroll
                for (int j = 0; j < 6; j++) {
                    w0[j] = expf(s0[j] - mx0); sum0 += w0[j];
                    w1[j] = expf(s1[j] - mx1); sum1 += w1[j];
                }
                const float i0 = 1.0f / sum0, i1 = 1.0f / sum1;
#pragma unroll
                for (int j = 0; j < 6; j++) { w0[j] *= i0; w1[j] *= i1; }
            }

            float a0[8] = {0,0,0,0,0,0,0,0}, a1[8] = {0,0,0,0,0,0,0,0};
#pragma unroll
            for (int j = 0; j < 6; j++) {
                const float2 f0 = __half22float2(*(const __half2*)&rv0[j].x);
                const float2 f1 = __half22float2(*(const __half2*)&rv0[j].y);
                const float2 f2 = __half22float2(*(const __half2*)&rv0[j].z);
                const float2 f3 = __half22float2(*(const __half2*)&rv0[j].w);
                a0[0] += w0[j] * f0.x; a0[1] += w0[j] * f0.y;
                a0[2] += w0[j] * f1.x; a0[3] += w0[j] * f1.y;
                a0[4] += w0[j] * f2.x; a0[5] += w0[j] * f2.y;
                a0[6] += w0[j] * f3.x; a0[7] += w0[j] * f3.y;
            }
#pragma unroll
            for (int j = 0; j < 6; j++) {
                const float2 f0 = __half22float2(*(const __half2*)&rv1[j].x);
                const float2 f1 = __half22float2(*(const __half2*)&rv1[j].y);
                const float2 f2 = __half22float2(*(const __half2*)&rv1[j].z);
                const float2 f3 = __half22float2(*(const __half2*)&rv1[j].w);
                a1[0] += w1[j] * f0.x; a1[1] += w1[j] * f0.y;
                a1[2] += w1[j] * f1.x; a1[3] += w1[j] * f1.y;
                a1[4] += w1[j] * f2.x; a1[5] += w1[j] * f2.y;
                a1[6] += w1[j] * f3.x; a1[7] += w1[j] * f3.y;
            }
            uint4 ov;
            *(__half2*)&ov.x = __floats2half2_rn(a0[0], a0[1]);
            *(__half2*)&ov.y = __floats2half2_rn(a0[2], a0[3]);
            *(__half2*)&ov.z = __floats2half2_rn(a0[4], a0[5]);
            *(__half2*)&ov.w = __floats2half2_rn(a0[6], a0[7]);
            *(uint4*)&sA[(wid * 8 + r0) * MP_LDA + lane * 8] = ov;
            *(__half2*)&ov.x = __floats2half2_rn(a1[0], a1[1]);
            *(__half2*)&ov.y = __floats2half2_rn(a1[2], a1[3]);
            *(__half2*)&ov.z = __floats2half2_rn(a1[4], a1[5]);
            *(__half2*)&ov.w = __floats2half2_rn(a1[6], a1[7]);
            *(uint4*)&sA[(wid * 8 + r1) * MP_LDA + lane * 8] = ov;
        }
    }

    CP_WAIT0();
    __syncthreads();      // sA + sWh + sred published; no more block syncs

    // ---- per-warp MMA: rows m0r..+15, cols nh..nh+127, K=256 ----
    float acc[16][4];
#pragma unroll
    for (int j = 0; j < 16; j++)
#pragma unroll
        for (int q = 0; q < 4; q++) acc[j][q] = 0.f;

    const int lrow = lane & 15;
    const int lcof = (lane >> 4) * 8;

    for (int kc = 0; kc < 16; kc++) {
        uint32_t fa[4];
        {
            const uint32_t ad = smem_u32(&sA[(m0r + lrow) * MP_LDA + kc * 16 + lcof]);
            asm volatile("ldmatrix.sync.aligned.m8n8.x4.shared.b16 {%0,%1,%2,%3}, [%4];"
                         : "=r"(fa[0]), "=r"(fa[1]), "=r"(fa[2]), "=r"(fa[3])
                         : "r"(ad));
        }
        uint32_t fb[16][2];
#pragma unroll
        for (int nt = 0; nt < 8; nt++) {
            const uint32_t ad = smem_u32(&sWh[(kc * 16 + lrow) * MP_LDB + nh + nt * 16 + lcof]);
            uint32_t r0, r1, r2, r3;
            asm volatile("ldmatrix.sync.aligned.m8n8.x4.trans.shared.b16 {%0,%1,%2,%3}, [%4];"
                         : "=r"(r0), "=r"(r1), "=r"(r2), "=r"(r3) : "r"(ad));
            fb[nt * 2][0] = r0; fb[nt * 2][1] = r1;
            fb[nt * 2 + 1][0] = r2; fb[nt * 2 + 1][1] = r3;
        }
#pragma unroll
        for (int j = 0; j < 16; j++)
            asm volatile(
                "mma.sync.aligned.m16n8k16.row.col.f32.f16.f16.f32 "
                "{%0,%1,%2,%3}, {%4,%5,%6,%7}, {%8,%9}, {%0,%1,%2,%3};"
                : "+f"(acc[j][0]), "+f"(acc[j][1]), "+f"(acc[j][2]), "+f"(acc[j][3])
                : "r"(fa[0]), "r"(fa[1]), "r"(fa[2]), "r"(fa[3]),
                  "r"(fb[j][0]), "r"(fb[j][1]));
    }

    // ---- epilogue ----
    float rowdot[2] = {0.f, 0.f};
    const int mrow = e0 + m0r + (lane >> 2);
#pragma unroll
    for (int j = 0; j < 16; j++) {
        const int nc = nh + j * 8 + (lane & 3) * 2;
        const float wx = __ldg(&wma[nc]);
        const float wy = __ldg(&wma[nc + 1]);
#pragma unroll
        for (int hf = 0; hf < 2; hf++) {
            const size_t m = (size_t)(mrow + hf * 8);
            float vx = acc[j][hf * 2 + 0];
            float vy = acc[j][hf * 2 + 1];
            const float2 d = __half22float2(*(const __half2*)&binput[m * 256 + nc]);
            vx = fmaxf(vx + d.x, 0.f);
            vy = fmaxf(vy + d.y, 0.f);
            *(__half2*)&msg_out[m * 256 + nc] = __floats2half2_rn(vx, vy);
            rowdot[hf] += vx * wx + vy * wy;
        }
    }
    if (scores_out) {
#pragma unroll
        for (int hf = 0; hf < 2; hf++) {
            float v = rowdot[hf];
            v += __shfl_xor_sync(0xffffffffu, v, 1);
            v += __shfl_xor_sync(0xffffffffu, v, 2);
            if ((lane & 3) == 0)
                atomicAdd(&sred[m0r + hf * 8 + (lane >> 2)], v);
        }
        __syncthreads();
        if (tid < 64) scores_out[e0 + tid] = sred[tid];
    }
}

// ---------------------------------------------------------------------------
__global__ void __launch_bounds__(256) atom_gather(
    const __half* __restrict__ msg, const int* __restrict__ agraph,
    __half* __restrict__ cat)
{
    const int ga   = (blockIdx.x * 256 + threadIdx.x) >> 5;
    const int lane = threadIdx.x & 31;
    if (ga >= N_ATOMS_) return;

    float a[8] = {0, 0, 0, 0, 0, 0, 0, 0};
#pragma unroll
    for (int j = 0; j < 6; j++) {
        const int nb = agraph[ga * 6 + j];
        const uint4 rv = *(const uint4*)(msg + (size_t)nb * 256 + lane * 8);
        const float2 f0 = __half22float2(*(const __half2*)&rv.x);
        const float2 f1 = __half22float2(*(const __half2*)&rv.y);
        const float2 f2 = __half22float2(*(const __half2*)&rv.z);
        const float2 f3 = __half22float2(*(const __half2*)&rv.w);
        a[0] += f0.x; a[1] += f0.y; a[2] += f1.x; a[3] += f1.y;
        a[4] += f2.x; a[5] += f2.y; a[6] += f3.x; a[7] += f3.y;
    }
    uint4 ov;
    *(__half2*)&ov.x = __floats2half2_rn(a[0], a[1]);
    *(__half2*)&ov.y = __floats2half2_rn(a[2], a[3]);
    *(__half2*)&ov.z = __floats2half2_rn(a[4], a[5]);
    *(__half2*)&ov.w = __floats2half2_rn(a[6], a[7]);
    *(uint4*)(cat + (size_t)ga * KCAT_P + 144 + lane * 8) = ov;
}

// ---------------------------------------------------------------------------
// Per-molecule self-attention (fp16 h input, 256-thread scores)
// ---------------------------------------------------------------------------
#define PAD 260
#define MOLATTN_SMEM ((2 * 32 * PAD + 32 * 32) * (int)sizeof(float))

__global__ void __launch_bounds__(256) mol_attn(
    const __half* __restrict__ atomh, const __half* __restrict__ hW,
    __half* __restrict__ t)
{
    extern __shared__ float sm[];
    float* sh = sm;
    float* sw = sm + 32 * PAD;
    float* sa = sm + 2 * 32 * PAD;

    const int b = blockIdx.x, tid = threadIdx.x;
    const __half* hb = atomh + (size_t)b * 32 * 256;
    const __half* wb = hW    + (size_t)b * 32 * 256;

    for (int i = tid; i < 32 * 256; i += 256) {
        const int a = i >> 8, k = i & 255;
        sh[a * PAD + k] = __half2float(hb[i]);
        sw[a * PAD + k] = __half2float(wb[i]);
    }
    __syncthreads();

    {
        const int a0 = (tid >> 4) * 2;
        const int c0 = (tid & 15) * 2;
        float acc[2][2] = {{0.f, 0.f}, {0.f, 0.f}};
        for (int k = 0; k < 256; k += 4) {
            float4 av0 = *(float4*)&sw[a0 * PAD + k];
            float4 av1 = *(float4*)&sw[(a0 + 1) * PAD + k];
            float4 bv0 = *(float4*)&sh[c0 * PAD + k];
            float4 bv1 = *(float4*)&sh[(c0 + 1) * PAD + k];
            acc[0][0] += av0.x * bv0.x + av0.y * bv0.y + av0.z * bv0.z + av0.w * bv0.w;
            acc[0][1] += av0.x * bv1.x + av0.y * bv1.y + av0.z * bv1.z + av0.w * bv1.w;
            acc[1][0] += av1.x * bv0.x + av1.y * bv0.y + av1.z * bv0.z + av1.w * bv0.w;
            acc[1][1] += av1.x * bv1.x + av1.y * bv1.y + av1.z * bv1.z + av1.w * bv1.w;
        }
        sa[a0 * 32 + c0]           = acc[0][0];
        sa[a0 * 32 + c0 + 1]       = acc[0][1];
        sa[(a0 + 1) * 32 + c0]     = acc[1][0];
        sa[(a0 + 1) * 32 + c0 + 1] = acc[1][1];
    }
    __syncthreads();

    const int wid = tid >> 5, lane = tid & 31;
    for (int a = wid; a < 32; a += 8) {
        float v = sa[a * 32 + lane];
        float m = v;
#pragma unroll
        for (int o = 16; o > 0; o >>= 1) m = fmaxf(m, __shfl_xor_sync(0xffffffffu, m, o));
        float ev = expf(v - m);
        float sum = ev;
#pragma unroll
        for (int o = 16; o > 0; o >>= 1) sum += __shfl_xor_sync(0xffffffffu, sum, o);
        sa[a * 32 + lane] = ev / sum;
    }
    __syncthreads();

    const int k = tid;
    float acc[32];
#pragma unroll
    for (int a = 0; a < 32; a++) acc[a] = 0.f;
    for (int c = 0; c < 32; c++) {
        const float hv = sh[c * PAD + k];
#pragma unroll
        for (int a = 0; a < 32; a++) acc[a] += sa[a * 32 + c] * hv;
    }
#pragma unroll
    for (int a = 0; a < 32; a++)
        t[((size_t)b * 32 + a) * 256 + k] = __float2half(acc[a]);
}

__global__ void __launch_bounds__(256) mol_reduce(
    const __half* __restrict__ atomh, const __half* __restrict__ atth,
    float* __restrict__ out)
{
    const int b = blockIdx.x, k = threadIdx.x;
    const __half* ph = atomh + (size_t)b * 32 * 256 + k;
    const __half* pa = atth  + (size_t)b * 32 * 256 + k;
    float s = 0.f;
#pragma unroll
    for (int a = 0; a < 32; a++)
        s += __half2float(ph[a * 256]) + __half2float(pa[a * 256]);
    out[(size_t)b * 256 + k] = s * (1.0f / 32.0f);
}

// ---------------------------------------------------------------------------
extern "C" void kernel_launch(void* const* d_in, const int* in_sizes, int n_in,
                              void* d_out, int out_size)
{
    const float* fatoms = (const float*)d_in[0];
    const float* fbonds = (const float*)d_in[1];
    const int*   agraph = (const int*)d_in[2];
    const int*   bgraph = (const int*)d_in[3];
    const float* W_i    = (const float*)d_in[5];
    const float* W_h    = (const float*)d_in[6];
    const float* W_o_w  = (const float*)d_in[7];
    const float* W_o_b  = (const float*)d_in[8];
    const float* W_a    = (const float*)d_in[9];
    const float* W_b_w  = (const float*)d_in[10];
    const float* W_b_b  = (const float*)d_in[11];
    const float* W_ma1  = (const float*)d_in[12];
    float* out = (float*)d_out;

    float* scratch = nullptr;
    cudaGetSymbolAddress((void**)&scratch, g_scratch);
    float* p = scratch;
    __half* binput_h = (__half*)p;            p += EH / 2;
    __half* msg0     = (__half*)p;            p += EH / 2;
    __half* msg1     = (__half*)p;            p += EH / 2;
    __half* fbonds_h = (__half*)p;            p += (size_t)E_BONDS * KIN_P / 2;
    __half* cat      = (__half*)p;            p += (size_t)N_ATOMS_ * KCAT_P / 2;
    __half* atomh_h  = (__half*)p;            p += NH / 2;
    __half* tmp_h    = (__half*)p;            p += NH / 2;
    __half* tbuf     = (__half*)p;            p += NH / 2;
    __half* atth     = (__half*)p;            p += NH / 2;
    float*  scores0  = p;                     p += E_BONDS;
    float*  scores1  = p;                     p += E_BONDS;
    __half* Wall     = (__half*)p;
    __half* Wh_h = Wall;
    __half* Wa_h = Wh_h + HID * 256;
    __half* Wb_h = Wa_h + HID * 256;
    __half* Wi_p = Wb_h + HID * 256;
    __half* Wo_p = Wi_p + KIN_P * 256;

    cudaFuncSetAttribute(mol_attn, cudaFuncAttributeMaxDynamicSharedMemorySize,
                         MOLATTN_SMEM);
    cudaFuncSetAttribute(mp_step, cudaFuncAttributeMaxDynamicSharedMemorySize,
                         MP_SMEM);
    cudaFuncSetAttribute(hgemm<false,true,true,true,true>,
                         cudaFuncAttributeMaxDynamicSharedMemorySize, HG_SMEM);
    cudaFuncSetAttribute(hgemm<true,true,true,false,false>,
                         cudaFuncAttributeMaxDynamicSharedMemorySize, HG_SMEM);
    cudaFuncSetAttribute(hgemm<false,false,true,false,false>,
                         cudaFuncAttributeMaxDynamicSharedMemorySize, HG_SMEM);

    w2h_all<<<(3 * HID * 256 + 255) / 256, 256>>>(W_h, W_a, W_b_w, Wall,
                                                  scores0, E_BONDS);
    build_wi<<<(KIN_P * 256 + 255) / 256, 256>>>(W_i, Wi_p);
    build_wo<<<(KCAT_P * 256 + 255) / 256, 256>>>(W_o_w, Wo_p);
    fb_conv<<<(E_BONDS * 20 + 255) / 256, 256>>>(fbonds, fbonds_h);
    fa_conv<<<(N_ATOMS_ * 22 + 255) / 256, 256>>>(fatoms, cat);

    const dim3 gE(E_BONDS / 128, 2);
    const dim3 gN(N_ATOMS_ / 128, 2);

    // G1: binput_h(raw) + msg0(relu) = fbonds_h @ Wi_p, fused scores0
    hgemm<false, true, true, true, true><<<gE, 256, HG_SMEM>>>(
        E_BONDS, KIN_P, fbonds_h, KIN_P, Wi_p, nullptr,
        msg0, binput_h, W_ma1, scores0);

    // 3 fused message-passing steps
    mp_step<<<E_BONDS / 64, 256, MP_SMEM>>>(msg0, bgraph, scores0, Wh_h,
                                            binput_h, msg1, W_ma1, scores1);
    mp_step<<<E_BONDS / 64, 256, MP_SMEM>>>(msg1, bgraph, scores1, Wh_h,
                                            binput_h, msg0, W_ma1, scores0);
    mp_step<<<E_BONDS / 64, 256, MP_SMEM>>>(msg0, bgraph, scores0, Wh_h,
                                            binput_h, msg1, W_ma1, nullptr);

    // atom readout
    atom_gather<<<N_ATOMS_ / 8, 256>>>(msg1, agraph, cat);
    hgemm<true, true, true, false, false><<<gN, 256, HG_SMEM>>>(
        N_ATOMS_, KCAT_P, cat, KCAT_P, Wo_p, W_o_b,
        atomh_h, nullptr, nullptr, nullptr);

    // molecule self-attention pooling
    hgemm<false, false, true, false, false><<<gN, 256, HG_SMEM>>>(
        N_ATOMS_, HID, atomh_h, HID, Wa_h, nullptr,
        tmp_h, nullptr, nullptr, nullptr);                        // hW
    mol_attn<<<BMOL, 256, MOLATTN_SMEM>>>(atomh_h, tmp_h, tbuf);  // t
    hgemm<true, true, true, false, false><<<gN, 256, HG_SMEM>>>(
        N_ATOMS_, HID, tbuf, HID, Wb_h, W_b_b,
        atth, nullptr, nullptr, nullptr);                         // att_h
    mol_reduce<<<BMOL, 256>>>(atomh_h, atth, out);
}

// round 14
// speedup vs baseline: 1.1459x; 1.1459x over previous
#include <cuda_runtime.h>
#include <cuda_fp16.h>
#include <cstdint>
#include <math.h>

#define E_BONDS   131072
#define N_ATOMS_  65536
#define HID       256
#define AFD       143
#define KIN       157
#define KIN_P     160
#define KCAT_P    416
#define BMOL      2048

#define EH  ((size_t)E_BONDS * HID)
#define NH  ((size_t)N_ATOMS_ * HID)
__device__ float g_scratch[127 * 1024 * 1024];

__device__ __forceinline__ uint32_t smem_u32(const void* p) {
    uint32_t a;
    asm("{ .reg .u64 t; cvta.to.shared.u64 t, %1; cvt.u32.u64 %0, t; }"
        : "=r"(a) : "l"(p));
    return a;
}
__device__ __forceinline__ void cp_async16(uint32_t dst, const void* src) {
    asm volatile("cp.async.cg.shared.global [%0], [%1], 16;"
                 :: "r"(dst), "l"(src));
}
#define CP_COMMIT() asm volatile("cp.async.commit_group;" ::: "memory")
#define CP_WAIT2()  asm volatile("cp.async.wait_group 2;" ::: "memory")
#define CP_WAIT1()  asm volatile("cp.async.wait_group 1;" ::: "memory")

// ---------------------------------------------------------------------------
// conversions / padding
// ---------------------------------------------------------------------------
__global__ void w2h_all(const float* __restrict__ s1, const float* __restrict__ s3,
                        const float* __restrict__ s4, __half* __restrict__ dst,
                        float* __restrict__ zbuf, int zn)
{
    int i = blockIdx.x * 256 + threadIdx.x;
    if (i < zn) zbuf[i] = 0.f;
    const int n1 = HID * 256, n3 = 2 * HID * 256, n4 = 3 * HID * 256;
    if (i >= n4) return;
    float v;
    if      (i < n1) v = s1[i];
    else if (i < n3) v = s3[i - n1];
    else             v = s4[i - n3];
    dst[i] = __float2half(v);
}

__global__ void build_wi(const float* __restrict__ W, __half* __restrict__ dst)
{
    int i = blockIdx.x * 256 + threadIdx.x;
    if (i >= KIN_P * 256) return;
    const int r = i >> 8;
    dst[i] = __float2half(r < KIN ? W[i] : 0.f);
}

__global__ void build_wo(const float* __restrict__ W, __half* __restrict__ dst)
{
    int i = blockIdx.x * 256 + threadIdx.x;
    if (i >= KCAT_P * 256) return;
    const int r = i >> 8, c = i & 255;
    float v = 0.f;
    if (r < 143)                  v = W[r * 256 + c];
    else if (r >= 144 && r < 400) v = W[(r - 1) * 256 + c];
    dst[i] = __float2half(v);
}

__global__ void fb_conv(const float* __restrict__ fb, __half* __restrict__ dst)
{
    int i = blockIdx.x * 256 + threadIdx.x;
    if (i >= E_BONDS * 20) return;
    const int e = i / 20, g = i - e * 20;
    const float* src = fb + (size_t)e * KIN + g * 8;
    __align__(16) __half hb[8];
#pragma unroll
    for (int k = 0; k < 8; k++) {
        const int c = g * 8 + k;
        hb[k] = __float2half(c < KIN ? src[k] : 0.f);
    }
    *(uint4*)&dst[(size_t)e * KIN_P + g * 8] = *(uint4*)hb;
}

// ---------------------------------------------------------------------------
// hgemm: 4-stage cp.async ring, K-chunk 32, block 128x128 (grid.y=2), fp16 A
// ---------------------------------------------------------------------------
#define LDA_H 40
#define LDB_H 136
#define SA_EL (128 * LDA_H)
#define SB_EL (32 * LDB_H)
#define ST_EL (SA_EL + SB_EL)
#define HG_SMEM (4 * ST_EL * 2)

template<bool HAS_BIAS, bool RELU, bool OUTH, bool RAWH, bool SCOREF>
__global__ void __launch_bounds__(256, 2) hgemm(
    int M, int K,
    const __half* __restrict__ Ah, int ldah,
    const __half* __restrict__ B,
    const float* __restrict__ bias,
    __half* __restrict__ outh,
    __half* __restrict__ rawh,
    const float* __restrict__ wma,
    float* __restrict__ scores_out)
{
    extern __shared__ __align__(16) __half smh[];

    const int tid  = threadIdx.x;
    const int wid  = tid >> 5;
    const int lane = tid & 31;
    const int m0   = blockIdx.x * 128;
    const int n0   = blockIdx.y * 128;
    const int wm   = (wid & 3) * 32;
    const int wn   = (wid >> 2) * 64;
    const int S    = K >> 5;

    float acc[2][8][4];
#pragma unroll
    for (int t = 0; t < 2; t++)
#pragma unroll
        for (int j = 0; j < 8; j++)
#pragma unroll
            for (int q = 0; q < 4; q++) acc[t][j][q] = 0.f;

    const int lrow = lane & 15;
    const int lcof = (lane >> 4) * 8;

    auto stage = [&](int s) {
        const int k0 = s * 32;
        __half* bA = smh + (s & 3) * ST_EL;
        __half* bB = bA + SA_EL;
#pragma unroll
        for (int it = 0; it < 2; it++) {
            const int id = tid + it * 256;
            const int r  = id >> 4;
            const int c8 = (id & 15) * 8;
            cp_async16(smem_u32(&bB[r * LDB_H + c8]),
                       &B[(size_t)(k0 + r) * 256 + n0 + c8]);
        }
#pragma unroll
        for (int it = 0; it < 2; it++) {
            const int id  = tid + it * 256;
            const int r   = id >> 2;
            const int c16 = (id & 3) * 8;
            cp_async16(smem_u32(&bA[r * LDA_H + c16]),
                       &Ah[(size_t)(m0 + r) * ldah + k0 + c16]);
        }
        CP_COMMIT();
    };

#pragma unroll
    for (int p = 0; p < 3; p++) {
        if (p < S) stage(p); else CP_COMMIT();
    }

    for (int s = 0; s < S; s++) {
        CP_WAIT2();
        __syncthreads();
        if (s + 3 < S) stage(s + 3); else CP_COMMIT();

        __half* bA = smh + (s & 3) * ST_EL;
        __half* bB = bA + SA_EL;
#pragma unroll
        for (int ks = 0; ks < 2; ks++) {
            uint32_t fa[2][4];
#pragma unroll
            for (int t = 0; t < 2; t++) {
                const uint32_t ad = smem_u32(&bA[(wm + t * 16 + lrow) * LDA_H + ks * 16 + lcof]);
                asm volatile("ldmatrix.sync.aligned.m8n8.x4.shared.b16 {%0,%1,%2,%3}, [%4];"
                             : "=r"(fa[t][0]), "=r"(fa[t][1]), "=r"(fa[t][2]), "=r"(fa[t][3])
                             : "r"(ad));
            }
            uint32_t fb[8][2];
#pragma unroll
            for (int nt = 0; nt < 4; nt++) {
                const uint32_t ad = smem_u32(&bB[(ks * 16 + lrow) * LDB_H + wn + nt * 16 + lcof]);
                uint32_t r0, r1, r2, r3;
                asm volatile("ldmatrix.sync.aligned.m8n8.x4.trans.shared.b16 {%0,%1,%2,%3}, [%4];"
                             : "=r"(r0), "=r"(r1), "=r"(r2), "=r"(r3) : "r"(ad));
                fb[nt * 2][0] = r0; fb[nt * 2][1] = r1;
                fb[nt * 2 + 1][0] = r2; fb[nt * 2 + 1][1] = r3;
            }
#pragma unroll
            for (int t = 0; t < 2; t++)
#pragma unroll
                for (int j = 0; j < 8; j++)
                    asm volatile(
                        "mma.sync.aligned.m16n8k16.row.col.f32.f16.f16.f32 "
                        "{%0,%1,%2,%3}, {%4,%5,%6,%7}, {%8,%9}, {%0,%1,%2,%3};"
                        : "+f"(acc[t][j][0]), "+f"(acc[t][j][1]),
                          "+f"(acc[t][j][2]), "+f"(acc[t][j][3])
                        : "r"(fa[t][0]), "r"(fa[t][1]), "r"(fa[t][2]), "r"(fa[t][3]),
                          "r"(fb[j][0]), "r"(fb[j][1]));
        }
    }

    float rowdot[2][2] = {{0.f, 0.f}, {0.f, 0.f}};
#pragma unroll
    for (int t = 0; t < 2; t++) {
        const int mrow = m0 + wm + t * 16 + (lane >> 2);
#pragma unroll
        for (int j = 0; j < 8; j++) {
            const int nc = n0 + wn + j * 8 + (lane & 3) * 2;
            float wx = 0.f, wy = 0.f;
            if (SCOREF) { wx = __ldg(&wma[nc]); wy = __ldg(&wma[nc + 1]); }
#pragma unroll
            for (int hf = 0; hf < 2; hf++) {
                const size_t m = (size_t)(mrow + hf * 8);
                float vx = acc[t][j][hf * 2 + 0];
                float vy = acc[t][j][hf * 2 + 1];
                if (HAS_BIAS) { vx += bias[nc]; vy += bias[nc + 1]; }
                if (RAWH) *(__half2*)&rawh[m * 256 + nc] = __floats2half2_rn(vx, vy);
                if (RELU) { vx = fmaxf(vx, 0.f); vy = fmaxf(vy, 0.f); }
                if (OUTH) *(__half2*)&outh[m * 256 + nc] = __floats2half2_rn(vx, vy);
                if (SCOREF) rowdot[t][hf] += vx * wx + vy * wy;
            }
        }
    }
    if (SCOREF) {
#pragma unroll
        for (int t = 0; t < 2; t++)
#pragma unroll
            for (int hf = 0; hf < 2; hf++) {
                float v = rowdot[t][hf];
                v += __shfl_xor_sync(0xffffffffu, v, 1);
                v += __shfl_xor_sync(0xffffffffu, v, 2);
                if ((lane & 3) == 0)
                    atomicAdd(&scores_out[m0 + wm + t * 16 + hf * 8 + (lane >> 2)], v);
            }
    }
}

// ---------------------------------------------------------------------------
// FUSED message-passing step (R12 structure: 3-stage B ring, 2 CTAs/SM)
// ---------------------------------------------------------------------------
#define MP_LDA 264
#define MP_LDB 264
#define MP_SA  (64 * MP_LDA)
#define MP_SB  (32 * MP_LDB)
#define MP_SMEM ((MP_SA + 3 * MP_SB) * 2)

__global__ void __launch_bounds__(256, 2) mp_step(
    const __half* __restrict__ msg, const int* __restrict__ bgraph,
    const float* __restrict__ scores, const __half* __restrict__ Wh,
    const __half* __restrict__ binput, __half* __restrict__ msg_out,
    const float* __restrict__ wma, float* __restrict__ scores_out)
{
    extern __shared__ __align__(16) __half smh[];
    __shared__ float sred[64];
    __half* sA = smh;
    __half* sBr = smh + MP_SA;

    const int tid  = threadIdx.x;
    const int wid  = tid >> 5;
    const int lane = tid & 31;
    const int e0   = blockIdx.x * 64;
    const int wm   = (wid & 1) * 32;
    const int wn   = (wid >> 1) * 64;

    if (tid < 64) sred[tid] = 0.f;

    auto stageB = [&](int s) {
        const int k0 = s * 32;
        __half* bB = sBr + (s % 3) * MP_SB;
#pragma unroll
        for (int it = 0; it < 4; it++) {
            const int id = tid + it * 256;
            const int r  = id >> 5;
            const int c8 = (id & 31) * 8;
            cp_async16(smem_u32(&bB[r * MP_LDB + c8]),
                       &Wh[(size_t)(k0 + r) * 256 + c8]);
        }
        CP_COMMIT();
    };

    stageB(0); stageB(1);

    // ---- gather: 2-row software pipeline ----
    {
        int   idxr[8];
        float scr[8];
#pragma unroll
        for (int rr = 0; rr < 8; rr++) {
            const int e = e0 + wid * 8 + rr;
            int id = 0; float sc = 0.f;
            if (lane < 6) {
                id = bgraph[e * 6 + lane];
                sc = __ldg(&scores[id]);
            }
            idxr[rr] = id; scr[rr] = sc;
        }
#pragma unroll
        for (int pr = 0; pr < 4; pr++) {
            const int r0 = pr * 2, r1 = pr * 2 + 1;
            int   nb0[6], nb1[6];
            float s0[6], s1[6];
#pragma unroll
            for (int j = 0; j < 6; j++) {
                nb0[j] = __shfl_sync(0xffffffffu, idxr[r0], j);
                s0[j]  = __shfl_sync(0xffffffffu, scr[r0], j);
                nb1[j] = __shfl_sync(0xffffffffu, idxr[r1], j);
                s1[j]  = __shfl_sync(0xffffffffu, scr[r1], j);
            }
            uint4 rv0[6], rv1[6];
#pragma unroll
            for (int j = 0; j < 6; j++)
                rv0[j] = *(const uint4*)(msg + (size_t)nb0[j] * 256 + lane * 8);
#pragma unroll
            for (int j = 0; j < 6; j++)
                rv1[j] = *(const uint4*)(msg + (size_t)nb1[j] * 256 + lane * 8);

            float w0[6], w1[6];
            {
                float mx0 = s0[0], mx1 = s1[0];
#pragma unroll
                for (int j = 1; j < 6; j++) { mx0 = fmaxf(mx0, s0[j]); mx1 = fmaxf(mx1, s1[j]); }
                float sum0 = 0.f, sum1 = 0.f;
#pragma unroll
                for (int j = 0; j < 6; j++) {
                    w0[j] = expf(s0[j] - mx0); sum0 += w0[j];
                    w1[j] = expf(s1[j] - mx1); sum1 += w1[j];
                }
                const float i0 = 1.0f / sum0, i1 = 1.0f / sum1;
#pragma unroll
                for (int j = 0; j < 6; j++) { w0[j] *= i0; w1[j] *= i1; }
            }

            float a0[8] = {0,0,0,0,0,0,0,0}, a1[8] = {0,0,0,0,0,0,0,0};
#pragma unroll
            for (int j = 0; j < 6; j++) {
                const float2 f0 = __half22float2(*(const __half2*)&rv0[j].x);
                const float2 f1 = __half22float2(*(const __half2*)&rv0[j].y);
                const float2 f2 = __half22float2(*(const __half2*)&rv0[j].z);
                const float2 f3 = __half22float2(*(const __half2*)&rv0[j].w);
                a0[0] += w0[j] * f0.x; a0[1] += w0[j] * f0.y;
                a0[2] += w0[j] * f1.x; a0[3] += w0[j] * f1.y;
                a0[4] += w0[j] * f2.x; a0[5] += w0[j] * f2.y;
                a0[6] += w0[j] * f3.x; a0[7] += w0[j] * f3.y;
            }
#pragma unroll
            for (int j = 0; j < 6; j++) {
                const float2 f0 = __half22float2(*(const __half2*)&rv1[j].x);
                const float2 f1 = __half22float2(*(const __half2*)&rv1[j].y);
                const float2 f2 = __half22float2(*(const __half2*)&rv1[j].z);
                const float2 f3 = __half22float2(*(const __half2*)&rv1[j].w);
                a1[0] += w1[j] * f0.x; a1[1] += w1[j] * f0.y;
                a1[2] += w1[j] * f1.x; a1[3] += w1[j] * f1.y;
                a1[4] += w1[j] * f2.x; a1[5] += w1[j] * f2.y;
                a1[6] += w1[j] * f3.x; a1[7] += w1[j] * f3.y;
            }
            uint4 ov;
            *(__half2*)&ov.x = __floats2half2_rn(a0[0], a0[1]);
            *(__half2*)&ov.y = __floats2half2_rn(a0[2], a0[3]);
            *(__half2*)&ov.z = __floats2half2_rn(a0[4], a0[5]);
            *(__half2*)&ov.w = __floats2half2_rn(a0[6], a0[7]);
            *(uint4*)&sA[(wid * 8 + r0) * MP_LDA + lane * 8] = ov;
            *(__half2*)&ov.x = __floats2half2_rn(a1[0], a1[1]);
            *(__half2*)&ov.y = __floats2half2_rn(a1[2], a1[3]);
            *(__half2*)&ov.z = __floats2half2_rn(a1[4], a1[5]);
            *(__half2*)&ov.w = __floats2half2_rn(a1[6], a1[7]);
            *(uint4*)&sA[(wid * 8 + r1) * MP_LDA + lane * 8] = ov;
        }
    }

    float acc[2][8][4];
#pragma unroll
    for (int t = 0; t < 2; t++)
#pragma unroll
        for (int j = 0; j < 8; j++)
#pragma unroll
            for (int q = 0; q < 4; q++) acc[t][j][q] = 0.f;

    const int lrow = lane & 15;
    const int lcof = (lane >> 4) * 8;

    for (int s = 0; s < 8; s++) {
        CP_WAIT1();
        __syncthreads();
        if (s + 2 < 8) stageB(s + 2); else CP_COMMIT();

        __half* bB = sBr + (s % 3) * MP_SB;
#pragma unroll
        for (int ks = 0; ks < 2; ks++) {
            const int kcol = s * 32 + ks * 16;
            uint32_t fa[2][4];
#pragma unroll
            for (int t = 0; t < 2; t++) {
                const uint32_t ad = smem_u32(&sA[(wm + t * 16 + lrow) * MP_LDA + kcol + lcof]);
                asm volatile("ldmatrix.sync.aligned.m8n8.x4.shared.b16 {%0,%1,%2,%3}, [%4];"
                             : "=r"(fa[t][0]), "=r"(fa[t][1]), "=r"(fa[t][2]), "=r"(fa[t][3])
                             : "r"(ad));
            }
            uint32_t fb[8][2];
#pragma unroll
            for (int nt = 0; nt < 4; nt++) {
                const uint32_t ad = smem_u32(&bB[(ks * 16 + lrow) * MP_LDB + wn + nt * 16 + lcof]);
                uint32_t r0, r1, r2, r3;
                asm volatile("ldmatrix.sync.aligned.m8n8.x4.trans.shared.b16 {%0,%1,%2,%3}, [%4];"
                             : "=r"(r0), "=r"(r1), "=r"(r2), "=r"(r3) : "r"(ad));
                fb[nt * 2][0] = r0; fb[nt * 2][1] = r1;
                fb[nt * 2 + 1][0] = r2; fb[nt * 2 + 1][1] = r3;
            }
#pragma unroll
            for (int t = 0; t < 2; t++)
#pragma unroll
                for (int j = 0; j < 8; j++)
                    asm volatile(
                        "mma.sync.aligned.m16n8k16.row.col.f32.f16.f16.f32 "
                        "{%0,%1,%2,%3}, {%4,%5,%6,%7}, {%8,%9}, {%0,%1,%2,%3};"
                        : "+f"(acc[t][j][0]), "+f"(acc[t][j][1]),
                          "+f"(acc[t][j][2]), "+f"(acc[t][j][3])
                        : "r"(fa[t][0]), "r"(fa[t][1]), "r"(fa[t][2]), "r"(fa[t][3]),
                          "r"(fb[j][0]), "r"(fb[j][1]));
        }
    }

    float rowdot[2][2] = {{0.f, 0.f}, {0.f, 0.f}};
#pragma unroll
    for (int t = 0; t < 2; t++) {
        const int mrow = e0 + wm + t * 16 + (lane >> 2);
#pragma unroll
        for (int j = 0; j < 8; j++) {
            const int nc = wn + j * 8 + (lane & 3) * 2;
            const float wx = __ldg(&wma[nc]);
            const float wy = __ldg(&wma[nc + 1]);
#pragma unroll
            for (int hf = 0; hf < 2; hf++) {
                const size_t m = (size_t)(mrow + hf * 8);
                float vx = acc[t][j][hf * 2 + 0];
                float vy = acc[t][j][hf * 2 + 1];
                const float2 d = __half22float2(*(const __half2*)&binput[m * 256 + nc]);
                vx = fmaxf(vx + d.x, 0.f);
                vy = fmaxf(vy + d.y, 0.f);
                *(__half2*)&msg_out[m * 256 + nc] = __floats2half2_rn(vx, vy);
                rowdot[t][hf] += vx * wx + vy * wy;
            }
        }
    }
    if (scores_out) {
#pragma unroll
        for (int t = 0; t < 2; t++)
#pragma unroll
            for (int hf = 0; hf < 2; hf++) {
                float v = rowdot[t][hf];
                v += __shfl_xor_sync(0xffffffffu, v, 1);
                v += __shfl_xor_sync(0xffffffffu, v, 2);
                if ((lane & 3) == 0)
                    atomicAdd(&sred[wm + t * 16 + hf * 8 + (lane >> 2)], v);
            }
        __syncthreads();
        if (tid < 64) scores_out[e0 + tid] = sred[tid];
    }
}

// ---------------------------------------------------------------------------
// atom_gather + fused fatoms conversion: fills cat[n][0..142] (fp16 fatoms),
// cat[n][143]=0, cat[n][144..399]=sum msg, cat[n][400..415]=0
// ---------------------------------------------------------------------------
__global__ void __launch_bounds__(256) atom_gather(
    const __half* __restrict__ msg, const int* __restrict__ agraph,
    const float* __restrict__ fa, __half* __restrict__ cat)
{
    const int ga   = (blockIdx.x * 256 + threadIdx.x) >> 5;
    const int lane = threadIdx.x & 31;
    if (ga >= N_ATOMS_) return;

    // fatoms conversion: lanes 0..17 convert groups of 8 cols; 18,19 zero-pad tail
    if (lane < 18) {
        const float* src = fa + (size_t)ga * AFD + lane * 8;
        __align__(16) __half hb[8];
#pragma unroll
        for (int k = 0; k < 8; k++) {
            const int c = lane * 8 + k;
            hb[k] = __float2half(c < AFD ? src[k] : 0.f);
        }
        *(uint4*)&cat[(size_t)ga * KCAT_P + lane * 8] = *(uint4*)hb;
    } else if (lane < 20) {
        uint4 z = make_uint4(0, 0, 0, 0);
        *(uint4*)&cat[(size_t)ga * KCAT_P + 400 + (lane - 18) * 8] = z;
    }

    float a[8] = {0, 0, 0, 0, 0, 0, 0, 0};
#pragma unroll
    for (int j = 0; j < 6; j++) {
        const int nb = agraph[ga * 6 + j];
        const uint4 rv = *(const uint4*)(msg + (size_t)nb * 256 + lane * 8);
        const float2 f0 = __half22float2(*(const __half2*)&rv.x);
        const float2 f1 = __half22float2(*(const __half2*)&rv.y);
        const float2 f2 = __half22float2(*(const __half2*)&rv.z);
        const float2 f3 = __half22float2(*(const __half2*)&rv.w);
        a[0] += f0.x; a[1] += f0.y; a[2] += f1.x; a[3] += f1.y;
        a[4] += f2.x; a[5] += f2.y; a[6] += f3.x; a[7] += f3.y;
    }
    uint4 ov;
    *(__half2*)&ov.x = __floats2half2_rn(a[0], a[1]);
    *(__half2*)&ov.y = __floats2half2_rn(a[2], a[3]);
    *(__half2*)&ov.z = __floats2half2_rn(a[4], a[5]);
    *(__half2*)&ov.w = __floats2half2_rn(a[6], a[7]);
    *(uint4*)(cat + (size_t)ga * KCAT_P + 144 + lane * 8) = ov;
}

// ---------------------------------------------------------------------------
// Per-molecule self-attention (fp16 h input, 256-thread scores)
// ---------------------------------------------------------------------------
#define PAD 260
#define MOLATTN_SMEM ((2 * 32 * PAD + 32 * 32) * (int)sizeof(float))

__global__ void __launch_bounds__(256) mol_attn(
    const __half* __restrict__ atomh, const __half* __restrict__ hW,
    __half* __restrict__ t)
{
    extern __shared__ float sm[];
    float* sh = sm;
    float* sw = sm + 32 * PAD;
    float* sa = sm + 2 * 32 * PAD;

    const int b = blockIdx.x, tid = threadIdx.x;
    const __half* hb = atomh + (size_t)b * 32 * 256;
    const __half* wb = hW    + (size_t)b * 32 * 256;

    for (int i = tid; i < 32 * 256; i += 256) {
        const int a = i >> 8, k = i & 255;
        sh[a * PAD + k] = __half2float(hb[i]);
        sw[a * PAD + k] = __half2float(wb[i]);
    }
    __syncthreads();

    {
        const int a0 = (tid >> 4) * 2;
        const int c0 = (tid & 15) * 2;
        float acc[2][2] = {{0.f, 0.f}, {0.f, 0.f}};
        for (int k = 0; k < 256; k += 4) {
            float4 av0 = *(float4*)&sw[a0 * PAD + k];
            float4 av1 = *(float4*)&sw[(a0 + 1) * PAD + k];
            float4 bv0 = *(float4*)&sh[c0 * PAD + k];
            float4 bv1 = *(float4*)&sh[(c0 + 1) * PAD + k];
            acc[0][0] += av0.x * bv0.x + av0.y * bv0.y + av0.z * bv0.z + av0.w * bv0.w;
            acc[0][1] += av0.x * bv1.x + av0.y * bv1.y + av0.z * bv1.z + av0.w * bv1.w;
            acc[1][0] += av1.x * bv0.x + av1.y * bv0.y + av1.z * bv0.z + av1.w * bv0.w;
            acc[1][1] += av1.x * bv1.x + av1.y * bv1.y + av1.z * bv1.z + av1.w * bv1.w;
        }
        sa[a0 * 32 + c0]           = acc[0][0];
        sa[a0 * 32 + c0 + 1]       = acc[0][1];
        sa[(a0 + 1) * 32 + c0]     = acc[1][0];
        sa[(a0 + 1) * 32 + c0 + 1] = acc[1][1];
    }
    __syncthreads();

    const int wid = tid >> 5, lane = tid & 31;
    for (int a = wid; a < 32; a += 8) {
        float v = sa[a * 32 + lane];
        float m = v;
#pragma unroll
        for (int o = 16; o > 0; o >>= 1) m = fmaxf(m, __shfl_xor_sync(0xffffffffu, m, o));
        float ev = expf(v - m);
        float sum = ev;
#pragma unroll
        for (int o = 16; o > 0; o >>= 1) sum += __shfl_xor_sync(0xffffffffu, sum, o);
        sa[a * 32 + lane] = ev / sum;
    }
    __syncthreads();

    const int k = tid;
    float acc[32];
#pragma unroll
    for (int a = 0; a < 32; a++) acc[a] = 0.f;
    for (int c = 0; c < 32; c++) {
        const float hv = sh[c * PAD + k];
#pragma unroll
        for (int a = 0; a < 32; a++) acc[a] += sa[a * 32 + c] * hv;
    }
#pragma unroll
    for (int a = 0; a < 32; a++)
        t[((size_t)b * 32 + a) * 256 + k] = __float2half(acc[a]);
}

__global__ void __launch_bounds__(256) mol_reduce(
    const __half* __restrict__ atomh, const __half* __restrict__ atth,
    float* __restrict__ out)
{
    const int b = blockIdx.x, k = threadIdx.x;
    const __half* ph = atomh + (size_t)b * 32 * 256 + k;
    const __half* pa = atth  + (size_t)b * 32 * 256 + k;
    float s = 0.f;
#pragma unroll
    for (int a = 0; a < 32; a++)
        s += __half2float(ph[a * 256]) + __half2float(pa[a * 256]);
    out[(size_t)b * 256 + k] = s * (1.0f / 32.0f);
}

// ---------------------------------------------------------------------------
extern "C" void kernel_launch(void* const* d_in, const int* in_sizes, int n_in,
                              void* d_out, int out_size)
{
    const float* fatoms = (const float*)d_in[0];
    const float* fbonds = (const float*)d_in[1];
    const int*   agraph = (const int*)d_in[2];
    const int*   bgraph = (const int*)d_in[3];
    const float* W_i    = (const float*)d_in[5];
    const float* W_h    = (const float*)d_in[6];
    const float* W_o_w  = (const float*)d_in[7];
    const float* W_o_b  = (const float*)d_in[8];
    const float* W_a    = (const float*)d_in[9];
    const float* W_b_w  = (const float*)d_in[10];
    const float* W_b_b  = (const float*)d_in[11];
    const float* W_ma1  = (const float*)d_in[12];
    float* out = (float*)d_out;

    float* scratch = nullptr;
    cudaGetSymbolAddress((void**)&scratch, g_scratch);
    float* p = scratch;
    __half* binput_h = (__half*)p;            p += EH / 2;
    __half* msg0     = (__half*)p;            p += EH / 2;
    __half* msg1     = (__half*)p;            p += EH / 2;
    __half* fbonds_h = (__half*)p;            p += (size_t)E_BONDS * KIN_P / 2;
    __half* cat      = (__half*)p;            p += (size_t)N_ATOMS_ * KCAT_P / 2;
    __half* atomh_h  = (__half*)p;            p += NH / 2;
    __half* tmp_h    = (__half*)p;            p += NH / 2;
    __half* tbuf     = (__half*)p;            p += NH / 2;
    __half* atth     = (__half*)p;            p += NH / 2;
    float*  scores0  = p;                     p += E_BONDS;
    float*  scores1  = p;                     p += E_BONDS;
    __half* Wall     = (__half*)p;
    __half* Wh_h = Wall;
    __half* Wa_h = Wh_h + HID * 256;
    __half* Wb_h = Wa_h + HID * 256;
    __half* Wi_p = Wb_h + HID * 256;
    __half* Wo_p = Wi_p + KIN_P * 256;

    cudaFuncSetAttribute(mol_attn, cudaFuncAttributeMaxDynamicSharedMemorySize,
                         MOLATTN_SMEM);
    cudaFuncSetAttribute(mp_step, cudaFuncAttributeMaxDynamicSharedMemorySize,
                         MP_SMEM);
    cudaFuncSetAttribute(hgemm<false,true,true,true,true>,
                         cudaFuncAttributeMaxDynamicSharedMemorySize, HG_SMEM);
    cudaFuncSetAttribute(hgemm<true,true,true,false,false>,
                         cudaFuncAttributeMaxDynamicSharedMemorySize, HG_SMEM);
    cudaFuncSetAttribute(hgemm<false,false,true,false,false>,
                         cudaFuncAttributeMaxDynamicSharedMemorySize, HG_SMEM);

    w2h_all<<<(3 * HID * 256 + 255) / 256, 256>>>(W_h, W_a, W_b_w, Wall,
                                                  scores0, E_BONDS);
    build_wi<<<(KIN_P * 256 + 255) / 256, 256>>>(W_i, Wi_p);
    build_wo<<<(KCAT_P * 256 + 255) / 256, 256>>>(W_o_w, Wo_p);
    fb_conv<<<(E_BONDS * 20 + 255) / 256, 256>>>(fbonds, fbonds_h);

    const dim3 gE(E_BONDS / 128, 2);
    const dim3 gN(N_ATOMS_ / 128, 2);

    // G1: binput_h(raw) + msg0(relu) = fbonds_h @ Wi_p, fused scores0
    hgemm<false, true, true, true, true><<<gE, 256, HG_SMEM>>>(
        E_BONDS, KIN_P, fbonds_h, KIN_P, Wi_p, nullptr,
        msg0, binput_h, W_ma1, scores0);

    // 3 fused message-passing steps
    mp_step<<<E_BONDS / 64, 256, MP_SMEM>>>(msg0, bgraph, scores0, Wh_h,
                                            binput_h, msg1, W_ma1, scores1);
    mp_step<<<E_BONDS / 64, 256, MP_SMEM>>>(msg1, bgraph, scores1, Wh_h,
                                            binput_h, msg0, W_ma1, scores0);
    mp_step<<<E_BONDS / 64, 256, MP_SMEM>>>(msg0, bgraph, scores0, Wh_h,
                                            binput_h, msg1, W_ma1, nullptr);

    // atom readout (fatoms conversion fused into the gather)
    atom_gather<<<N_ATOMS_ / 8, 256>>>(msg1, agraph, fatoms, cat);
    hgemm<true, true, true, false, false><<<gN, 256, HG_SMEM>>>(
        N_ATOMS_, KCAT_P, cat, KCAT_P, Wo_p, W_o_b,
        atomh_h, nullptr, nullptr, nullptr);

    // molecule self-attention pooling
    hgemm<false, false, true, false, false><<<gN, 256, HG_SMEM>>>(
        N_ATOMS_, HID, atomh_h, HID, Wa_h, nullptr,
        tmp_h, nullptr, nullptr, nullptr);                        // hW
    mol_attn<<<BMOL, 256, MOLATTN_SMEM>>>(atomh_h, tmp_h, tbuf);  // t
    hgemm<true, true, true, false, false><<<gN, 256, HG_SMEM>>>(
        N_ATOMS_, HID, tbuf, HID, Wb_h, W_b_b,
        atth, nullptr, nullptr, nullptr);                         // att_h
    mol_reduce<<<BMOL, 256>>>(atomh_h, atth, out);
}